// round 15
// baseline (speedup 1.0000x reference)
#include <cuda_runtime.h>
#include <cuda_fp16.h>
#include <cstdint>

#define NB 8
#define NS 2048
#define ND 1024

// ---------------- scratch (device globals; raw-bit storage, no class types) ----
__device__ unsigned short g_seqh[NB*NS*ND];
__device__ unsigned short g_wqh[ND*ND], g_wkh[ND*ND], g_wvh[ND*ND], g_woh[ND*ND];
__device__ unsigned short g_qh[NB*NS*ND];
__device__ unsigned short g_kh[NB*NS*ND];
__device__ unsigned short g_vth[NB*NS*ND];                  // V^T: [B][D][S]
__device__ unsigned short g_sch[NB*NS*NS];                  // unnormalized exp (fp16)
__device__ unsigned short g_posth[NB*NS*ND];                // post (fp16)
__device__ unsigned short g_attnh[NB*NS*ND];                // attn (fp16)
__device__ unsigned short g_ffnh[NB*NS*ND];                 // ffn (fp16)
__device__ float g_sc[NB*NS*NS];
__device__ float g_inv[NB*NS];                              // per-row 1/sum

// ---------------- helpers ----------------
__device__ __forceinline__ uint32_t smem_u32(const void* p) {
    uint32_t a;
    asm("{ .reg .u64 t; cvta.to.shared.u64 t, %1; cvt.u32.u64 %0, t; }" : "=r"(a) : "l"(p));
    return a;
}

#define CP_ASYNC16(s, g) \
    asm volatile("cp.async.cg.shared.global [%0], [%1], 16;" :: "r"(s), "l"(g) : "memory")
#define CP_COMMIT() asm volatile("cp.async.commit_group;" ::: "memory")
#define CP_WAIT1()  asm volatile("cp.async.wait_group 1;" ::: "memory")

__device__ __forceinline__ void ldmx4(uint32_t r[4], uint32_t a) {
    asm volatile("ldmatrix.sync.aligned.m8n8.x4.shared.b16 {%0,%1,%2,%3}, [%4];"
        : "=r"(r[0]), "=r"(r[1]), "=r"(r[2]), "=r"(r[3]) : "r"(a));
}

__device__ __forceinline__ void mma16816(float c[4], const uint32_t a[4],
                                         uint32_t b0, uint32_t b1) {
    asm volatile("mma.sync.aligned.m16n8k16.row.col.f32.f16.f16.f32 "
        "{%0,%1,%2,%3}, {%4,%5,%6,%7}, {%8,%9}, {%0,%1,%2,%3};"
        : "+f"(c[0]), "+f"(c[1]), "+f"(c[2]), "+f"(c[3])
        : "r"(a[0]), "r"(a[1]), "r"(a[2]), "r"(a[3]), "r"(b0), "r"(b1));
}

__device__ __forceinline__ unsigned short h_hi(float x) {
    return __half_as_ushort(__float2half_rn(x));
}
__device__ __forceinline__ uint32_t pack2(unsigned short a, unsigned short b) {
    return (uint32_t)a | ((uint32_t)b << 16);
}
__device__ __forceinline__ float h2f(unsigned short u) {
    return __half2float(__ushort_as_half(u));
}

// ---------------- single-fp16 GEMM (NT): C = alpha * A @ B^T ----------------
// 512 threads, 4x4 warp grid, 32x32 warp tile, 128x128x64 CTA tile (proven R13 body).
// modes: 0 fp32*alpha; 5 single+bias fp16; 6 transposed single+bias fp16 ([B][D][S]);
//        7 rowscale fp16 out (PV: out = acc*rs[row]); 4 bias+relu+fp16resid -> fp16 out.
// lenmode: 1 skip n-tiles >= len (scores); 2 truncate K at len (PV);
//          3 skip m-tiles whose in-batch row >= len (K/V projections).
#define BKE 64
#define TILE_B 16384         // 128 rows * 64 halves * 2B
#define STAGE_B (2*TILE_B)   // A, B
#define NSTG 3
#define GEMM_SMEM (NSTG*STAGE_B)   // 98304
#define GT 512

#define SW8(row, c) (((c) ^ (row)) & 7)

__global__ void __launch_bounds__(GT, 1) gemm_h1(
    const unsigned short* __restrict__ Ah,
    const unsigned short* __restrict__ Bh,
    int K, long sA, long sB,
    int mode, float alpha, const float* __restrict__ bias,
    float* __restrict__ C, long strideC, int ldc,
    unsigned short* __restrict__ Coh,
    const unsigned short* __restrict__ Rh,
    const float* __restrict__ rs,
    const int* __restrict__ lens, int lenmode)
{
    extern __shared__ char smem[];
    const int t = threadIdx.x, wid = t >> 5, l = t & 31;
    const int m0 = blockIdx.y * 128, n0 = blockIdx.x * 128, bz = blockIdx.z;

    int nc = K / BKE;
    if (lenmode == 1) { if (n0 >= __ldg(lens + bz)) return; }
    if (lenmode == 2) { int len = __ldg(lens + bz); int kk = (len + BKE - 1) & ~(BKE - 1); if (kk < K) nc = kk / BKE; }
    if (lenmode == 3) { if ((m0 & (NS - 1)) >= __ldg(lens + (m0 >> 11))) return; }

    const unsigned short* pAh = Ah + (long)bz * sA;
    const unsigned short* pBh = Bh + (long)bz * sB;

    const uint32_t sb = smem_u32(smem);
    const int wm = (wid & 3) * 32, wn = (wid >> 2) * 32;   // 4x4 warp grid

    float acc[2][4][4];
#pragma unroll
    for (int i = 0; i < 2; i++)
#pragma unroll
        for (int j = 0; j < 4; j++)
#pragma unroll
            for (int e = 0; e < 4; e++) acc[i][j][e] = 0.f;

    auto issue = [&](int c, int s) {
        const long k0 = (long)c * BKE;
        const uint32_t stg = sb + (uint32_t)s * STAGE_B;
#pragma unroll
        for (int j = 0; j < 2; j++) {
            int idx = t + j * GT;
            int row = idx >> 3, ch = idx & 7;          // 128-B rows, 8 x 16-B chunks
            uint32_t off = (uint32_t)row * 128 + (SW8(row, ch) << 4);
            long ga = (long)(m0 + row) * K + k0 + ch * 8;
            long gb = (long)(n0 + row) * K + k0 + ch * 8;
            CP_ASYNC16(stg + off,          (const void*)(pAh + ga));
            CP_ASYNC16(stg + TILE_B + off, (const void*)(pBh + gb));
        }
    };

    issue(0, 0); CP_COMMIT();
    if (nc > 1) issue(1, 1);
    CP_COMMIT();

    for (int i = 0; i < nc; i++) {
        CP_WAIT1();
        __syncthreads();
        const uint32_t stg = sb + (uint32_t)(i % NSTG) * STAGE_B;
#pragma unroll
        for (int sub = 0; sub < 4; sub++) {
            uint32_t ahf[2][4], bhf[2][4];
            const int ch = sub * 2 + (l >> 4);
#pragma unroll
            for (int mt = 0; mt < 2; mt++) {
                int r = wm + mt * 16 + (l & 15);
                uint32_t off = (uint32_t)r * 128 + (SW8(r, ch) << 4);
                ldmx4(ahf[mt], stg + off);
            }
#pragma unroll
            for (int bt = 0; bt < 2; bt++) {
                int r = wn + bt * 16 + (l & 15);
                uint32_t off = (uint32_t)r * 128 + (SW8(r, ch) << 4);
                ldmx4(bhf[bt], stg + TILE_B + off);
            }
#pragma unroll
            for (int mt = 0; mt < 2; mt++)
#pragma unroll
                for (int bt = 0; bt < 2; bt++) {
                    mma16816(acc[mt][2 * bt],     ahf[mt], bhf[bt][0], bhf[bt][2]);
                    mma16816(acc[mt][2 * bt + 1], ahf[mt], bhf[bt][1], bhf[bt][3]);
                }
        }
        if (i + 2 < nc) issue(i + 2, (i + 2) % NSTG);
        CP_COMMIT();
    }

    // ---------------- epilogue ----------------
#pragma unroll
    for (int mt = 0; mt < 2; mt++) {
#pragma unroll
        for (int nt = 0; nt < 4; nt++) {
            const int col = n0 + wn + nt * 8 + (l & 3) * 2;
#pragma unroll
            for (int h = 0; h < 2; h++) {
                const int row = m0 + wm + mt * 16 + (l >> 2) + h * 8;
                float v0 = acc[mt][nt][h * 2], v1 = acc[mt][nt][h * 2 + 1];
                if (mode == 0) {
                    float2 o = make_float2(v0 * alpha, v1 * alpha);
                    *(float2*)(C + (long)bz * strideC + (long)row * ldc + col) = o;
                } else if (mode == 5) {            // single+bias fp16
                    *(uint32_t*)(Coh + (long)row * ldc + col) =
                        pack2(h_hi(v0 + __ldg(bias + col)), h_hi(v1 + __ldg(bias + col + 1)));
                } else if (mode == 6) {            // transposed single+bias fp16
                    int b = row >> 11, s = row & (NS - 1);
                    long a0 = ((long)b * ND + col) * (long)NS + s;
                    Coh[a0]      = h_hi(v0 + __ldg(bias + col));
                    Coh[a0 + NS] = h_hi(v1 + __ldg(bias + col + 1));
                } else if (mode == 7) {            // PV: rowscale fp16 out
                    float scl = __ldg(rs + bz * NS + row);
                    *(uint32_t*)(Coh + (long)bz * strideC + (long)row * ldc + col) =
                        pack2(h_hi(v0 * scl), h_hi(v1 * scl));
                } else {                           // mode 4: bias+relu+fp16resid -> fp16
                    long a = (long)row * ldc + col;
                    uint32_t rr = *(const uint32_t*)(Rh + a);
                    float o0 = fmaxf(v0 + __ldg(bias + col), 0.f) + h2f((unsigned short)(rr & 0xFFFF));
                    float o1 = fmaxf(v1 + __ldg(bias + col + 1), 0.f) + h2f((unsigned short)(rr >> 16));
                    *(uint32_t*)(Coh + a) = pack2(h_hi(o0), h_hi(o1));
                }
            }
        }
    }
}

// ---------------- elementwise: round fp32 -> fp16 bits ----------------
__global__ void round_h(const float* __restrict__ x, unsigned short* __restrict__ h, int n4)
{
    int i = blockIdx.x * 256 + threadIdx.x;
    if (i >= n4) return;
    float4 v = ((const float4*)x)[i];
    ((uint32_t*)h)[2 * i]     = pack2(h_hi(v.x), h_hi(v.y));
    ((uint32_t*)h)[2 * i + 1] = pack2(h_hi(v.z), h_hi(v.w));
}

// ---------------- masked row softmax: 2 passes, unnormalized exp + inv ----------------
__global__ void softmax_rows(const float* __restrict__ sc, unsigned short* __restrict__ sch,
                             float* __restrict__ inv_out, const int* __restrict__ lens)
{
    __shared__ float red[256];
    const int t = threadIdx.x;
    const int q = blockIdx.x, b = blockIdx.y;
    const long base = ((long)b * NS + q) * NS;
    const float* row = sc + base;
    const int len = __ldg(lens + b);
    const int wlim = (len + BKE - 1) & ~(BKE - 1);   // PV never reads past this

    float m = -3.4e38f;
    for (int j = t; j < len; j += 256) m = fmaxf(m, row[j]);
    red[t] = m; __syncthreads();
    for (int s = 128; s > 0; s >>= 1) {
        if (t < s) red[t] = fmaxf(red[t], red[t + s]);
        __syncthreads();
    }
    m = red[0]; __syncthreads();

    float sum = 0.f;
    for (int j = t; j < len; j += 256) {
        float e = __expf(row[j] - m);
        sum += e;
        sch[base + j] = h_hi(e);                     // unnormalized, <= 1
    }
    for (int j = len + t; j < wlim; j += 256) sch[base + j] = 0;
    red[t] = sum; __syncthreads();
    for (int s = 128; s > 0; s >>= 1) {
        if (t < s) red[t] += red[t + s];
        __syncthreads();
    }
    if (t == 0) inv_out[b * NS + q] = 1.0f / red[0];
}

// ---------------- fp16-x (optional fp32 resid) + LayerNorm ----------------
__global__ void add_ln_h(const unsigned short* __restrict__ xh, const float* __restrict__ res,
                         const float* __restrict__ g, const float* __restrict__ bt,
                         float* __restrict__ out, unsigned short* __restrict__ outh)
{
    __shared__ float r1[256], r2[256];
    const int t = threadIdx.x;
    const long row = blockIdx.x;

    uint2 xr = ((const uint2*)(xh + row * ND))[t];
    float4 v;
    v.x = h2f((unsigned short)(xr.x & 0xFFFF));
    v.y = h2f((unsigned short)(xr.x >> 16));
    v.z = h2f((unsigned short)(xr.y & 0xFFFF));
    v.w = h2f((unsigned short)(xr.y >> 16));
    if (res) {
        float4 w = ((const float4*)(res + row * ND))[t];
        v.x += w.x; v.y += w.y; v.z += w.z; v.w += w.w;
    }
    float s  = v.x + v.y + v.z + v.w;
    float ss = v.x * v.x + v.y * v.y + v.z * v.z + v.w * v.w;
    r1[t] = s; r2[t] = ss; __syncthreads();
    for (int k = 128; k > 0; k >>= 1) {
        if (t < k) { r1[t] += r1[t + k]; r2[t] += r2[t + k]; }
        __syncthreads();
    }
    const float mean = r1[0] * (1.0f / ND);
    const float var  = r2[0] * (1.0f / ND) - mean * mean;
    const float inv  = rsqrtf(var + 1e-5f);

    float4 gg = ((const float4*)g)[t];
    float4 bb = ((const float4*)bt)[t];
    float4 o;
    o.x = (v.x - mean) * inv * gg.x + bb.x;
    o.y = (v.y - mean) * inv * gg.y + bb.y;
    o.z = (v.z - mean) * inv * gg.z + bb.z;
    o.w = (v.w - mean) * inv * gg.w + bb.w;
    if (out) ((float4*)(out + row * ND))[t] = o;
    if (outh) {
        long p = row * (ND / 2) + 2 * t;
        ((uint32_t*)outh)[p]     = pack2(h_hi(o.x), h_hi(o.y));
        ((uint32_t*)outh)[p + 1] = pack2(h_hi(o.z), h_hi(o.w));
    }
}

// ---------------- launch ----------------
extern "C" void kernel_launch(void* const* d_in, const int* in_sizes, int n_in,
                              void* d_out, int out_size)
{
    const float* seq  = (const float*)d_in[0];
    const int*   lens = (const int*)  d_in[1];
    const float* Wq = (const float*)d_in[2];
    const float* bq = (const float*)d_in[3];
    const float* Wk = (const float*)d_in[4];
    const float* bk = (const float*)d_in[5];
    const float* Wv = (const float*)d_in[6];
    const float* bv = (const float*)d_in[7];
    const float* Wo = (const float*)d_in[8];
    const float* bo = (const float*)d_in[9];
    const float* g1 = (const float*)d_in[10];
    const float* b1 = (const float*)d_in[11];
    const float* g2 = (const float*)d_in[12];
    const float* b2 = (const float*)d_in[13];
    float* out = (float*)d_out;

    static bool init_done = false;
    if (!init_done) {
        cudaFuncSetAttribute(gemm_h1, cudaFuncAttributeMaxDynamicSharedMemorySize, GEMM_SMEM);
        init_done = true;
    }

    struct Ptrs {
        unsigned short *seqh, *wqh, *wkh, *wvh, *woh;
        unsigned short *qh, *kh, *vth, *sch, *posth, *attnh, *ffnh;
        float *sc, *inv;
    };
    static Ptrs P;
    static bool sym_done = false;
    if (!sym_done) {
        cudaGetSymbolAddress((void**)&P.seqh, g_seqh);
        cudaGetSymbolAddress((void**)&P.wqh,  g_wqh);    cudaGetSymbolAddress((void**)&P.wkh,  g_wkh);
        cudaGetSymbolAddress((void**)&P.wvh,  g_wvh);    cudaGetSymbolAddress((void**)&P.woh,  g_woh);
        cudaGetSymbolAddress((void**)&P.qh,   g_qh);     cudaGetSymbolAddress((void**)&P.kh,   g_kh);
        cudaGetSymbolAddress((void**)&P.vth,  g_vth);    cudaGetSymbolAddress((void**)&P.sch,  g_sch);
        cudaGetSymbolAddress((void**)&P.posth,g_posth);  cudaGetSymbolAddress((void**)&P.attnh,g_attnh);
        cudaGetSymbolAddress((void**)&P.ffnh, g_ffnh);
        cudaGetSymbolAddress((void**)&P.sc,   g_sc);     cudaGetSymbolAddress((void**)&P.inv,  g_inv);
        sym_done = true;
    }

    const long SD  = (long)NS * ND;
    const long SS2 = (long)NS * NS;

    // ---- prepare operands (single fp16 round) ----
    round_h<<<(NB * NS * ND) / 1024, 256>>>(seq, P.seqh, NB * NS * ND / 4);
    round_h<<<(ND * ND) / 1024, 256>>>(Wq, P.wqh, ND * ND / 4);
    round_h<<<(ND * ND) / 1024, 256>>>(Wk, P.wkh, ND * ND / 4);
    round_h<<<(ND * ND) / 1024, 256>>>(Wv, P.wvh, ND * ND / 4);
    round_h<<<(ND * ND) / 1024, 256>>>(Wo, P.woh, ND * ND / 4);

    const dim3 blk(GT);
    const dim3 gproj(ND / 128, (NB * NS) / 128, 1);

    // Q projection; K, V projections skip masked-out rows
    gemm_h1<<<gproj, blk, GEMM_SMEM>>>(P.seqh, P.wqh, ND, 0, 0,
        5, 1.f, bq, nullptr, 0, ND, P.qh, nullptr, nullptr, nullptr, 0);
    gemm_h1<<<gproj, blk, GEMM_SMEM>>>(P.seqh, P.wkh, ND, 0, 0,
        5, 1.f, bk, nullptr, 0, ND, P.kh, nullptr, nullptr, lens, 3);
    gemm_h1<<<gproj, blk, GEMM_SMEM>>>(P.seqh, P.wvh, ND, 0, 0,
        6, 1.f, bv, nullptr, 0, ND, P.vth, nullptr, nullptr, lens, 3);

    // scores = Q K^T / 32 (masked n-tiles skipped)
    gemm_h1<<<dim3(NS / 128, NS / 128, NB), blk, GEMM_SMEM>>>(
        P.qh, P.kh, ND, SD, SD,
        0, 1.0f / 32.0f, nullptr, P.sc, SS2, NS, nullptr, nullptr, nullptr, lens, 1);

    // 2-pass softmax: unnormalized exp fp16 + per-row inv
    softmax_rows<<<dim3(NS, NB), 256>>>(P.sc, P.sch, P.inv, lens);

    // attn = (P_unnorm @ V) * inv[row], fp16 out (K truncated at len)
    gemm_h1<<<dim3(ND / 128, NS / 128, NB), blk, GEMM_SMEM>>>(
        P.sch, P.vth, NS, SS2, SD,
        7, 1.f, nullptr, nullptr, SD, ND, P.attnh, nullptr, P.inv, lens, 2);

    // post = LN(seq + attn) -> fp16 (A-operand AND residual for FFN)
    add_ln_h<<<NB * NS, 256>>>(P.attnh, seq, g1, b1, nullptr, P.posth);

    // ffn = relu(post @ Wo^T + bo) + post -> fp16
    gemm_h1<<<gproj, blk, GEMM_SMEM>>>(P.posth, P.woh, ND, 0, 0,
        4, 1.f, bo, nullptr, 0, ND, P.ffnh, P.posth, nullptr, nullptr, 0);

    // out = LN(ffn)
    add_ln_h<<<NB * NS, 256>>>(P.ffnh, nullptr, g2, b2, out, nullptr);
}